// round 6
// baseline (speedup 1.0000x reference)
#include <cuda_runtime.h>
#include <math.h>

#define NN 50000
#define HH 128
#define EE 800000
#define ECC 200000
#define STRIDE 64           // max in-degree bucket (Poisson(16): P(>64) ~ 1e-20)

// ---------------- scratch (no allocations allowed) ----------------
__device__ float g_tmp[NN * HH];       // GEMM output (message to send)
__device__ float g_h[NN * HH];         // hidden after layer 1
__device__ float g_dego[NN];           // deg_out^{-1/2}
__device__ float g_degi[NN];           // deg_in^{-1/2}
__device__ int   g_cnt_out[NN];        // int out-degree
__device__ int   g_fill[NN];           // ELL fill cursor == in-degree
__device__ int   g_ell[NN * STRIDE];   // per-dst src lists, fixed stride

// ---------------- degree / ELL kernels ----------------
__global__ void zero_cnt_kernel() {
    int i = blockIdx.x * blockDim.x + threadIdx.x;
    if (i < NN) { g_cnt_out[i] = 0; g_fill[i] = 0; }
}

// single edge pass: out-degree count + ELL bucket fill (fill cursor = in-degree)
__global__ void build_graph_kernel(const int* __restrict__ src, const int* __restrict__ dst) {
    int i = blockIdx.x * blockDim.x + threadIdx.x;
    if (i < EE) {
        int s = src[i], d = dst[i];
        atomicAdd(&g_cnt_out[s], 1);
        int p = atomicAdd(&g_fill[d], 1);
        if (p < STRIDE) g_ell[d * STRIDE + p] = s;
    }
}

__global__ void make_scale_kernel() {
    int i = blockIdx.x * blockDim.x + threadIdx.x;
    if (i < NN) {
        int co = g_cnt_out[i]; if (co < 1) co = 1;
        int ci = g_fill[i];    if (ci < 1) ci = 1;
        g_dego[i] = rsqrtf((float)co);
        g_degi[i] = rsqrtf((float)ci);
    }
}

// ---------------- GEMM: g_tmp = (A @ W) [* dego[row] if apply_scale] ----------------
// 512 threads, tile 128x128, each thread 2 rows x 16 cols.
// sA padded to 132 floats/row (33 float4): float4-aligned rows, k-reads bank-clean.
__global__ __launch_bounds__(512) void gemm128_kernel(
    const float* __restrict__ A_ext, int use_gh,
    const float* __restrict__ W, int n, int apply_scale)
{
    extern __shared__ float sm[];
    float* sW = sm;                 // 128*128 floats (64 KB)
    float* sA = sm + 128 * 128;     // 128*132 floats (67.6 KB)

    const float* A = use_gh ? g_h : A_ext;
    int t = threadIdx.x;
    int row0 = blockIdx.x * 128;

    // load W: 4096 float4, 8 per thread, coalesced
    for (int i = t; i < 128 * 32; i += 512)
        ((float4*)sW)[i] = ((const float4*)W)[i];

    // load A tile as float4 into padded rows (33 float4 per row)
    for (int i = t; i < 128 * 32; i += 512) {
        int r = i >> 5, c4 = i & 31;
        int row = row0 + r;
        float4 v = make_float4(0.f, 0.f, 0.f, 0.f);
        if (row < n) v = ((const float4*)A)[(size_t)row * 32 + c4];
        ((float4*)sA)[r * 33 + c4] = v;
    }
    __syncthreads();

    int rl = t >> 3;            // 0..63 : rows rl and rl+64
    int cb = (t & 7) * 4;       // float4 col-group: cols cb*4 + {0..15}
    const float4* sW4 = (const float4*)sW;

    float acc0[16], acc1[16];
    #pragma unroll
    for (int j = 0; j < 16; ++j) { acc0[j] = 0.f; acc1[j] = 0.f; }

    #pragma unroll 4
    for (int k = 0; k < 128; ++k) {
        float4 w0 = sW4[k * 32 + cb    ];
        float4 w1 = sW4[k * 32 + cb + 1];
        float4 w2 = sW4[k * 32 + cb + 2];
        float4 w3 = sW4[k * 32 + cb + 3];
        float a0 = sA[rl * 132 + k];
        float a1 = sA[(rl + 64) * 132 + k];
        acc0[ 0] = fmaf(a0, w0.x, acc0[ 0]); acc1[ 0] = fmaf(a1, w0.x, acc1[ 0]);
        acc0[ 1] = fmaf(a0, w0.y, acc0[ 1]); acc1[ 1] = fmaf(a1, w0.y, acc1[ 1]);
        acc0[ 2] = fmaf(a0, w0.z, acc0[ 2]); acc1[ 2] = fmaf(a1, w0.z, acc1[ 2]);
        acc0[ 3] = fmaf(a0, w0.w, acc0[ 3]); acc1[ 3] = fmaf(a1, w0.w, acc1[ 3]);
        acc0[ 4] = fmaf(a0, w1.x, acc0[ 4]); acc1[ 4] = fmaf(a1, w1.x, acc1[ 4]);
        acc0[ 5] = fmaf(a0, w1.y, acc0[ 5]); acc1[ 5] = fmaf(a1, w1.y, acc1[ 5]);
        acc0[ 6] = fmaf(a0, w1.z, acc0[ 6]); acc1[ 6] = fmaf(a1, w1.z, acc1[ 6]);
        acc0[ 7] = fmaf(a0, w1.w, acc0[ 7]); acc1[ 7] = fmaf(a1, w1.w, acc1[ 7]);
        acc0[ 8] = fmaf(a0, w2.x, acc0[ 8]); acc1[ 8] = fmaf(a1, w2.x, acc1[ 8]);
        acc0[ 9] = fmaf(a0, w2.y, acc0[ 9]); acc1[ 9] = fmaf(a1, w2.y, acc1[ 9]);
        acc0[10] = fmaf(a0, w2.z, acc0[10]); acc1[10] = fmaf(a1, w2.z, acc1[10]);
        acc0[11] = fmaf(a0, w2.w, acc0[11]); acc1[11] = fmaf(a1, w2.w, acc1[11]);
        acc0[12] = fmaf(a0, w3.x, acc0[12]); acc1[12] = fmaf(a1, w3.x, acc1[12]);
        acc0[13] = fmaf(a0, w3.y, acc0[13]); acc1[13] = fmaf(a1, w3.y, acc1[13]);
        acc0[14] = fmaf(a0, w3.z, acc0[14]); acc1[14] = fmaf(a1, w3.z, acc1[14]);
        acc0[15] = fmaf(a0, w3.w, acc0[15]); acc1[15] = fmaf(a1, w3.w, acc1[15]);
    }

    int colbase = (t & 7) * 16;
    int rowA = row0 + rl;
    int rowB = rowA + 64;
    if (rowA < n) {
        float s = apply_scale ? g_dego[rowA] : 1.0f;
        float4* o = (float4*)(g_tmp + (size_t)rowA * 128 + colbase);
        o[0] = make_float4(acc0[0]*s,  acc0[1]*s,  acc0[2]*s,  acc0[3]*s);
        o[1] = make_float4(acc0[4]*s,  acc0[5]*s,  acc0[6]*s,  acc0[7]*s);
        o[2] = make_float4(acc0[8]*s,  acc0[9]*s,  acc0[10]*s, acc0[11]*s);
        o[3] = make_float4(acc0[12]*s, acc0[13]*s, acc0[14]*s, acc0[15]*s);
    }
    if (rowB < n) {
        float s = apply_scale ? g_dego[rowB] : 1.0f;
        float4* o = (float4*)(g_tmp + (size_t)rowB * 128 + colbase);
        o[0] = make_float4(acc1[0]*s,  acc1[1]*s,  acc1[2]*s,  acc1[3]*s);
        o[1] = make_float4(acc1[4]*s,  acc1[5]*s,  acc1[6]*s,  acc1[7]*s);
        o[2] = make_float4(acc1[8]*s,  acc1[9]*s,  acc1[10]*s, acc1[11]*s);
        o[3] = make_float4(acc1[12]*s, acc1[13]*s, acc1[14]*s, acc1[15]*s);
    }
}

// ---------------- gather-aggregate + finalize ----------------
// one warp per dst node; src_scale=1 applies dego[s] per edge (layer 1)
__global__ __launch_bounds__(256) void gather_kernel(
    const float* __restrict__ b, float* __restrict__ dst_ext, int src_scale)
{
    int v = blockIdx.x * 8 + (threadIdx.x >> 5);
    if (v >= NN) return;
    int lane = threadIdx.x & 31;

    int cnt = g_fill[v];
    if (cnt > STRIDE) cnt = STRIDE;
    const int* lst = g_ell + (size_t)v * STRIDE;

    float4 acc = make_float4(0.f, 0.f, 0.f, 0.f);
    if (src_scale) {
        int j = 0;
        for (; j + 1 < cnt; j += 2) {
            int s0 = lst[j], s1 = lst[j + 1];
            float c0 = g_dego[s0], c1 = g_dego[s1];
            float4 a0 = ((const float4*)(g_tmp + (size_t)s0 * 128))[lane];
            float4 a1 = ((const float4*)(g_tmp + (size_t)s1 * 128))[lane];
            acc.x = fmaf(a0.x, c0, fmaf(a1.x, c1, acc.x));
            acc.y = fmaf(a0.y, c0, fmaf(a1.y, c1, acc.y));
            acc.z = fmaf(a0.z, c0, fmaf(a1.z, c1, acc.z));
            acc.w = fmaf(a0.w, c0, fmaf(a1.w, c1, acc.w));
        }
        for (; j < cnt; ++j) {
            int s = lst[j];
            float c = g_dego[s];
            float4 a = ((const float4*)(g_tmp + (size_t)s * 128))[lane];
            acc.x = fmaf(a.x, c, acc.x); acc.y = fmaf(a.y, c, acc.y);
            acc.z = fmaf(a.z, c, acc.z); acc.w = fmaf(a.w, c, acc.w);
        }
    } else {
        int j = 0;
        for (; j + 3 < cnt; j += 4) {
            int s0 = lst[j], s1 = lst[j + 1], s2 = lst[j + 2], s3 = lst[j + 3];
            float4 a0 = ((const float4*)(g_tmp + (size_t)s0 * 128))[lane];
            float4 a1 = ((const float4*)(g_tmp + (size_t)s1 * 128))[lane];
            float4 a2 = ((const float4*)(g_tmp + (size_t)s2 * 128))[lane];
            float4 a3 = ((const float4*)(g_tmp + (size_t)s3 * 128))[lane];
            acc.x += a0.x + a1.x + a2.x + a3.x;
            acc.y += a0.y + a1.y + a2.y + a3.y;
            acc.z += a0.z + a1.z + a2.z + a3.z;
            acc.w += a0.w + a1.w + a2.w + a3.w;
        }
        for (; j < cnt; ++j) {
            int s = lst[j];
            float4 a = ((const float4*)(g_tmp + (size_t)s * 128))[lane];
            acc.x += a.x; acc.y += a.y; acc.z += a.z; acc.w += a.w;
        }
    }

    float sc = g_degi[v];
    float4 bb = ((const float4*)b)[lane];
    float4 o;
    o.x = fmaf(acc.x, sc, bb.x); o.x = o.x > 0.f ? o.x : 0.f;
    o.y = fmaf(acc.y, sc, bb.y); o.y = o.y > 0.f ? o.y : 0.f;
    o.z = fmaf(acc.z, sc, bb.z); o.z = o.z > 0.f ? o.z : 0.f;
    o.w = fmaf(acc.w, sc, bb.w); o.w = o.w > 0.f ? o.w : 0.f;

    float* dst = dst_ext ? dst_ext : g_h;
    ((float4*)(dst + (size_t)v * 128))[lane] = o;
}

// ---------------- edge classifier ----------------
__global__ __launch_bounds__(256) void edge_cls_kernel(
    const float* __restrict__ h,
    const int* __restrict__ cs, const int* __restrict__ cd,
    const float* __restrict__ Wc, const float* __restrict__ bc,
    float* __restrict__ out)
{
    int w = threadIdx.x >> 5, lane = threadIdx.x & 31;
    int i = blockIdx.x * 8 + w;
    if (i >= ECC) return;

    int k0 = lane * 4;
    float w0s[4], w1s[4], w0d[4], w1d[4];
    #pragma unroll
    for (int j = 0; j < 4; ++j) {
        w0s[j] = __ldg(&Wc[(k0 + j) * 2    ]);
        w1s[j] = __ldg(&Wc[(k0 + j) * 2 + 1]);
        w0d[j] = __ldg(&Wc[(128 + k0 + j) * 2    ]);
        w1d[j] = __ldg(&Wc[(128 + k0 + j) * 2 + 1]);
    }

    int s = __ldg(&cs[i]);
    int d = __ldg(&cd[i]);
    float4 a = ((const float4*)(h + (size_t)s * 128))[lane];
    float4 b = ((const float4*)(h + (size_t)d * 128))[lane];

    float l0 = a.x * w0s[0] + a.y * w0s[1] + a.z * w0s[2] + a.w * w0s[3]
             + b.x * w0d[0] + b.y * w0d[1] + b.z * w0d[2] + b.w * w0d[3];
    float l1 = a.x * w1s[0] + a.y * w1s[1] + a.z * w1s[2] + a.w * w1s[3]
             + b.x * w1d[0] + b.y * w1d[1] + b.z * w1d[2] + b.w * w1d[3];

    #pragma unroll
    for (int m = 16; m > 0; m >>= 1) {
        l0 += __shfl_xor_sync(0xffffffffu, l0, m);
        l1 += __shfl_xor_sync(0xffffffffu, l1, m);
    }

    if (lane == 0) {
        float z0 = l0 + __ldg(&bc[0]);
        float z1 = l1 + __ldg(&bc[1]);
        out[(size_t)i * 2    ] = 1.0f / (1.0f + expf(-z0));
        out[(size_t)i * 2 + 1] = 1.0f / (1.0f + expf(-z1));
    }
}

// ---------------- launch ----------------
extern "C" void kernel_launch(void* const* d_in, const int* in_sizes, int n_in,
                              void* d_out, int out_size)
{
    const float* feat = (const float*)d_in[0];
    const int*   gsrc = (const int*)  d_in[1];
    const int*   gdst = (const int*)  d_in[2];
    const int*   csrc = (const int*)  d_in[3];
    const int*   cdst = (const int*)  d_in[4];
    const float* W1   = (const float*)d_in[5];
    const float* b1   = (const float*)d_in[6];
    const float* W2   = (const float*)d_in[7];
    const float* b2   = (const float*)d_in[8];
    const float* Wc   = (const float*)d_in[9];
    const float* bc   = (const float*)d_in[10];
    float* out = (float*)d_out;

    const int GEMM_SMEM = (128 * 128 + 128 * 132) * 4;  // 133,120 B
    static int attr_done = 0;
    if (!attr_done) {
        cudaFuncSetAttribute(gemm128_kernel,
                             cudaFuncAttributeMaxDynamicSharedMemorySize, GEMM_SMEM);
        attr_done = 1;
    }

    // graph build
    zero_cnt_kernel<<<(NN + 255) / 256, 256>>>();                       // launch 0
    build_graph_kernel<<<(EE + 255) / 256, 256>>>(gsrc, gdst);          // launch 1
    make_scale_kernel<<<(NN + 255) / 256, 256>>>();                     // launch 2

    // GEMM1 (unscaled; dego applied per-edge in gather1) — launch index 3 for ncu
    gemm128_kernel<<<(NN + 127) / 128, 512, GEMM_SMEM>>>(feat, 0, W1, NN, 0);    // launch 3

    // layer 1 aggregate (applies dego[src] per edge) -> g_h
    gather_kernel<<<(NN + 7) / 8, 256>>>(b1, nullptr, 1);               // launch 4

    // layer 2
    gemm128_kernel<<<(NN + 127) / 128, 512, GEMM_SMEM>>>(nullptr, 1, W2, NN, 1); // launch 5
    gather_kernel<<<(NN + 7) / 8, 256>>>(b2, out, 0);                   // launch 6

    // edge classifier
    edge_cls_kernel<<<(ECC + 7) / 8, 256>>>(out, csrc, cdst, Wc, bc,
                                            out + (size_t)NN * HH);     // launch 7
}

// round 9
// speedup vs baseline: 1.8871x; 1.8871x over previous
#include <cuda_runtime.h>
#include <math.h>

#define NN 50000
#define HH 128
#define EE 800000
#define ECC 200000
#define STRIDE 64           // max in-degree bucket (Poisson(16): P(>64) ~ 1e-20)

// ---------------- scratch (no allocations allowed) ----------------
__device__ float g_tmp[NN * HH];       // GEMM output (message to send)
__device__ float g_h[NN * HH];         // hidden after layer 1
__device__ float g_dego[NN];           // deg_out^{-1/2}
__device__ float g_degi[NN];           // deg_in^{-1/2}
__device__ int   g_cnt_out[NN];        // int out-degree
__device__ int   g_fill[NN];           // ELL fill cursor == in-degree
__device__ int   g_ell[NN * STRIDE];   // per-dst src lists, fixed stride

// ---------------- degree / ELL kernels ----------------
__global__ void zero_cnt_kernel() {
    int i = blockIdx.x * blockDim.x + threadIdx.x;
    if (i < NN) { g_cnt_out[i] = 0; g_fill[i] = 0; }
}

// single edge pass: out-degree count + ELL bucket fill (fill cursor = in-degree)
__global__ void build_graph_kernel(const int* __restrict__ src, const int* __restrict__ dst) {
    int i = blockIdx.x * blockDim.x + threadIdx.x;
    if (i < EE) {
        int s = src[i], d = dst[i];
        atomicAdd(&g_cnt_out[s], 1);
        int p = atomicAdd(&g_fill[d], 1);
        if (p < STRIDE) g_ell[d * STRIDE + p] = s;
    }
}

__global__ void make_scale_kernel() {
    int i = blockIdx.x * blockDim.x + threadIdx.x;
    if (i < NN) {
        int co = g_cnt_out[i]; if (co < 1) co = 1;
        int ci = g_fill[i];    if (ci < 1) ci = 1;
        g_dego[i] = rsqrtf((float)co);
        g_degi[i] = rsqrtf((float)ci);
    }
}

// ---------------- GEMM: g_tmp = (A @ W) [* dego[row] if apply_scale] ----------------
// 512 threads, tile 128x128, each thread 2 rows x 16 cols.
// cb = t&7: thread owns float4 col-groups {cb, cb+8, cb+16, cb+24} -> warp's
// LDS.128 of W hits 8 CONSECUTIVE float4s = one 128B segment = all 32 banks.
// sA padded to 132 floats/row: k-column reads land on 4 distinct banks (8-way bcast).
__global__ __launch_bounds__(512) void gemm128_kernel(
    const float* __restrict__ A_ext, int use_gh,
    const float* __restrict__ W, int n, int apply_scale)
{
    extern __shared__ float sm[];
    float* sW = sm;                 // 128*128 floats (64 KB)
    float* sA = sm + 128 * 128;     // 128*132 floats (67.6 KB)

    const float* A = use_gh ? g_h : A_ext;
    int t = threadIdx.x;
    int row0 = blockIdx.x * 128;

    // load W: 4096 float4, 8 per thread, coalesced
    for (int i = t; i < 128 * 32; i += 512)
        ((float4*)sW)[i] = ((const float4*)W)[i];

    // load A tile as float4 into padded rows (33 float4 per row)
    for (int i = t; i < 128 * 32; i += 512) {
        int r = i >> 5, c4 = i & 31;
        int row = row0 + r;
        float4 v = make_float4(0.f, 0.f, 0.f, 0.f);
        if (row < n) v = ((const float4*)A)[(size_t)row * 32 + c4];
        ((float4*)sA)[r * 33 + c4] = v;
    }
    __syncthreads();

    int rl = t >> 3;        // 0..63 : rows rl and rl+64
    int cb = t & 7;         // float4 col-groups cb + 8j, j=0..3
    const float4* sW4 = (const float4*)sW;

    float4 acc0[4], acc1[4];
    #pragma unroll
    for (int j = 0; j < 4; ++j) {
        acc0[j] = make_float4(0.f, 0.f, 0.f, 0.f);
        acc1[j] = make_float4(0.f, 0.f, 0.f, 0.f);
    }

    #pragma unroll 4
    for (int k = 0; k < 128; ++k) {
        float4 w0 = sW4[k * 32 + cb     ];
        float4 w1 = sW4[k * 32 + cb +  8];
        float4 w2 = sW4[k * 32 + cb + 16];
        float4 w3 = sW4[k * 32 + cb + 24];
        float a0 = sA[rl * 132 + k];
        float a1 = sA[(rl + 64) * 132 + k];
        acc0[0].x = fmaf(a0, w0.x, acc0[0].x); acc1[0].x = fmaf(a1, w0.x, acc1[0].x);
        acc0[0].y = fmaf(a0, w0.y, acc0[0].y); acc1[0].y = fmaf(a1, w0.y, acc1[0].y);
        acc0[0].z = fmaf(a0, w0.z, acc0[0].z); acc1[0].z = fmaf(a1, w0.z, acc1[0].z);
        acc0[0].w = fmaf(a0, w0.w, acc0[0].w); acc1[0].w = fmaf(a1, w0.w, acc1[0].w);
        acc0[1].x = fmaf(a0, w1.x, acc0[1].x); acc1[1].x = fmaf(a1, w1.x, acc1[1].x);
        acc0[1].y = fmaf(a0, w1.y, acc0[1].y); acc1[1].y = fmaf(a1, w1.y, acc1[1].y);
        acc0[1].z = fmaf(a0, w1.z, acc0[1].z); acc1[1].z = fmaf(a1, w1.z, acc1[1].z);
        acc0[1].w = fmaf(a0, w1.w, acc0[1].w); acc1[1].w = fmaf(a1, w1.w, acc1[1].w);
        acc0[2].x = fmaf(a0, w2.x, acc0[2].x); acc1[2].x = fmaf(a1, w2.x, acc1[2].x);
        acc0[2].y = fmaf(a0, w2.y, acc0[2].y); acc1[2].y = fmaf(a1, w2.y, acc1[2].y);
        acc0[2].z = fmaf(a0, w2.z, acc0[2].z); acc1[2].z = fmaf(a1, w2.z, acc1[2].z);
        acc0[2].w = fmaf(a0, w2.w, acc0[2].w); acc1[2].w = fmaf(a1, w2.w, acc1[2].w);
        acc0[3].x = fmaf(a0, w3.x, acc0[3].x); acc1[3].x = fmaf(a1, w3.x, acc1[3].x);
        acc0[3].y = fmaf(a0, w3.y, acc0[3].y); acc1[3].y = fmaf(a1, w3.y, acc1[3].y);
        acc0[3].z = fmaf(a0, w3.z, acc0[3].z); acc1[3].z = fmaf(a1, w3.z, acc1[3].z);
        acc0[3].w = fmaf(a0, w3.w, acc0[3].w); acc1[3].w = fmaf(a1, w3.w, acc1[3].w);
    }

    int rowA = row0 + rl;
    int rowB = rowA + 64;
    if (rowA < n) {
        float s = apply_scale ? g_dego[rowA] : 1.0f;
        float4* o = (float4*)(g_tmp + (size_t)rowA * 128);
        #pragma unroll
        for (int j = 0; j < 4; ++j)
            o[cb + 8 * j] = make_float4(acc0[j].x * s, acc0[j].y * s,
                                        acc0[j].z * s, acc0[j].w * s);
    }
    if (rowB < n) {
        float s = apply_scale ? g_dego[rowB] : 1.0f;
        float4* o = (float4*)(g_tmp + (size_t)rowB * 128);
        #pragma unroll
        for (int j = 0; j < 4; ++j)
            o[cb + 8 * j] = make_float4(acc1[j].x * s, acc1[j].y * s,
                                        acc1[j].z * s, acc1[j].w * s);
    }
}

// ---------------- gather-aggregate + finalize ----------------
// one warp per dst node; src_scale=1 applies dego[s] per edge (layer 1)
__global__ __launch_bounds__(256) void gather_kernel(
    const float* __restrict__ b, float* __restrict__ dst_ext, int src_scale)
{
    int v = blockIdx.x * 8 + (threadIdx.x >> 5);
    if (v >= NN) return;
    int lane = threadIdx.x & 31;

    int cnt = g_fill[v];
    if (cnt > STRIDE) cnt = STRIDE;
    const int* lst = g_ell + (size_t)v * STRIDE;

    float4 acc = make_float4(0.f, 0.f, 0.f, 0.f);
    if (src_scale) {
        int j = 0;
        for (; j + 1 < cnt; j += 2) {
            int s0 = lst[j], s1 = lst[j + 1];
            float c0 = g_dego[s0], c1 = g_dego[s1];
            float4 a0 = ((const float4*)(g_tmp + (size_t)s0 * 128))[lane];
            float4 a1 = ((const float4*)(g_tmp + (size_t)s1 * 128))[lane];
            acc.x = fmaf(a0.x, c0, fmaf(a1.x, c1, acc.x));
            acc.y = fmaf(a0.y, c0, fmaf(a1.y, c1, acc.y));
            acc.z = fmaf(a0.z, c0, fmaf(a1.z, c1, acc.z));
            acc.w = fmaf(a0.w, c0, fmaf(a1.w, c1, acc.w));
        }
        for (; j < cnt; ++j) {
            int s = lst[j];
            float c = g_dego[s];
            float4 a = ((const float4*)(g_tmp + (size_t)s * 128))[lane];
            acc.x = fmaf(a.x, c, acc.x); acc.y = fmaf(a.y, c, acc.y);
            acc.z = fmaf(a.z, c, acc.z); acc.w = fmaf(a.w, c, acc.w);
        }
    } else {
        int j = 0;
        for (; j + 3 < cnt; j += 4) {
            int s0 = lst[j], s1 = lst[j + 1], s2 = lst[j + 2], s3 = lst[j + 3];
            float4 a0 = ((const float4*)(g_tmp + (size_t)s0 * 128))[lane];
            float4 a1 = ((const float4*)(g_tmp + (size_t)s1 * 128))[lane];
            float4 a2 = ((const float4*)(g_tmp + (size_t)s2 * 128))[lane];
            float4 a3 = ((const float4*)(g_tmp + (size_t)s3 * 128))[lane];
            acc.x += a0.x + a1.x + a2.x + a3.x;
            acc.y += a0.y + a1.y + a2.y + a3.y;
            acc.z += a0.z + a1.z + a2.z + a3.z;
            acc.w += a0.w + a1.w + a2.w + a3.w;
        }
        for (; j < cnt; ++j) {
            int s = lst[j];
            float4 a = ((const float4*)(g_tmp + (size_t)s * 128))[lane];
            acc.x += a.x; acc.y += a.y; acc.z += a.z; acc.w += a.w;
        }
    }

    float sc = g_degi[v];
    float4 bb = ((const float4*)b)[lane];
    float4 o;
    o.x = fmaf(acc.x, sc, bb.x); o.x = o.x > 0.f ? o.x : 0.f;
    o.y = fmaf(acc.y, sc, bb.y); o.y = o.y > 0.f ? o.y : 0.f;
    o.z = fmaf(acc.z, sc, bb.z); o.z = o.z > 0.f ? o.z : 0.f;
    o.w = fmaf(acc.w, sc, bb.w); o.w = o.w > 0.f ? o.w : 0.f;

    float* dst = dst_ext ? dst_ext : g_h;
    ((float4*)(dst + (size_t)v * 128))[lane] = o;
}

// ---------------- edge classifier ----------------
__global__ __launch_bounds__(256) void edge_cls_kernel(
    const float* __restrict__ h,
    const int* __restrict__ cs, const int* __restrict__ cd,
    const float* __restrict__ Wc, const float* __restrict__ bc,
    float* __restrict__ out)
{
    int w = threadIdx.x >> 5, lane = threadIdx.x & 31;
    int i = blockIdx.x * 8 + w;
    if (i >= ECC) return;

    int k0 = lane * 4;
    float w0s[4], w1s[4], w0d[4], w1d[4];
    #pragma unroll
    for (int j = 0; j < 4; ++j) {
        w0s[j] = __ldg(&Wc[(k0 + j) * 2    ]);
        w1s[j] = __ldg(&Wc[(k0 + j) * 2 + 1]);
        w0d[j] = __ldg(&Wc[(128 + k0 + j) * 2    ]);
        w1d[j] = __ldg(&Wc[(128 + k0 + j) * 2 + 1]);
    }

    int s = __ldg(&cs[i]);
    int d = __ldg(&cd[i]);
    float4 a = ((const float4*)(h + (size_t)s * 128))[lane];
    float4 b = ((const float4*)(h + (size_t)d * 128))[lane];

    float l0 = a.x * w0s[0] + a.y * w0s[1] + a.z * w0s[2] + a.w * w0s[3]
             + b.x * w0d[0] + b.y * w0d[1] + b.z * w0d[2] + b.w * w0d[3];
    float l1 = a.x * w1s[0] + a.y * w1s[1] + a.z * w1s[2] + a.w * w1s[3]
             + b.x * w1d[0] + b.y * w1d[1] + b.z * w1d[2] + b.w * w1d[3];

    #pragma unroll
    for (int m = 16; m > 0; m >>= 1) {
        l0 += __shfl_xor_sync(0xffffffffu, l0, m);
        l1 += __shfl_xor_sync(0xffffffffu, l1, m);
    }

    if (lane == 0) {
        float z0 = l0 + __ldg(&bc[0]);
        float z1 = l1 + __ldg(&bc[1]);
        out[(size_t)i * 2    ] = 1.0f / (1.0f + expf(-z0));
        out[(size_t)i * 2 + 1] = 1.0f / (1.0f + expf(-z1));
    }
}

// ---------------- launch ----------------
extern "C" void kernel_launch(void* const* d_in, const int* in_sizes, int n_in,
                              void* d_out, int out_size)
{
    const float* feat = (const float*)d_in[0];
    const int*   gsrc = (const int*)  d_in[1];
    const int*   gdst = (const int*)  d_in[2];
    const int*   csrc = (const int*)  d_in[3];
    const int*   cdst = (const int*)  d_in[4];
    const float* W1   = (const float*)d_in[5];
    const float* b1   = (const float*)d_in[6];
    const float* W2   = (const float*)d_in[7];
    const float* b2   = (const float*)d_in[8];
    const float* Wc   = (const float*)d_in[9];
    const float* bc   = (const float*)d_in[10];
    float* out = (float*)d_out;

    const int GEMM_SMEM = (128 * 128 + 128 * 132) * 4;  // 133,120 B
    static int attr_done = 0;
    if (!attr_done) {
        cudaFuncSetAttribute(gemm128_kernel,
                             cudaFuncAttributeMaxDynamicSharedMemorySize, GEMM_SMEM);
        attr_done = 1;
    }

    // graph build
    zero_cnt_kernel<<<(NN + 255) / 256, 256>>>();                       // launch 0
    build_graph_kernel<<<(EE + 255) / 256, 256>>>(gsrc, gdst);          // launch 1
    make_scale_kernel<<<(NN + 255) / 256, 256>>>();                     // launch 2

    // GEMM1 (unscaled; dego applied per-edge in gather1) — launch index 3 for ncu
    gemm128_kernel<<<(NN + 127) / 128, 512, GEMM_SMEM>>>(feat, 0, W1, NN, 0);    // launch 3

    // layer 1 aggregate (applies dego[src] per edge) -> g_h
    gather_kernel<<<(NN + 7) / 8, 256>>>(b1, nullptr, 1);               // launch 4

    // layer 2
    gemm128_kernel<<<(NN + 127) / 128, 512, GEMM_SMEM>>>(nullptr, 1, W2, NN, 1); // launch 5
    gather_kernel<<<(NN + 7) / 8, 256>>>(b2, out, 0);                   // launch 6

    // edge classifier
    edge_cls_kernel<<<(ECC + 7) / 8, 256>>>(out, csrc, cdst, Wc, bc,
                                            out + (size_t)NN * HH);     // launch 7
}

// round 10
// speedup vs baseline: 2.0993x; 1.1125x over previous
#include <cuda_runtime.h>
#include <math.h>

#define NN 50000
#define HH 128
#define EE 800000
#define ECC 200000
#define STRIDE 64           // max in-degree bucket (Poisson(16): P(>64) ~ 1e-20)

// ---------------- scratch (no allocations allowed) ----------------
__device__ float g_tmp[NN * HH];       // GEMM output (message to send)
__device__ float g_h[NN * HH];         // hidden after layer 1
__device__ float g_dego[NN];           // deg_out^{-1/2}
__device__ float g_degi[NN];           // deg_in^{-1/2}
__device__ int   g_cnt_out[NN];        // int out-degree
__device__ int   g_fill[NN];           // ELL fill cursor == in-degree
__device__ int   g_ell[NN * STRIDE];   // per-dst src lists, fixed stride

// ---------------- degree / ELL kernels ----------------
__global__ void zero_cnt_kernel() {
    int i = blockIdx.x * blockDim.x + threadIdx.x;
    if (i < NN) { g_cnt_out[i] = 0; g_fill[i] = 0; }
}

// single edge pass: out-degree count + ELL bucket fill (fill cursor = in-degree)
__global__ void build_graph_kernel(const int* __restrict__ src, const int* __restrict__ dst) {
    int i = blockIdx.x * blockDim.x + threadIdx.x;
    if (i < EE) {
        int s = src[i], d = dst[i];
        atomicAdd(&g_cnt_out[s], 1);
        int p = atomicAdd(&g_fill[d], 1);
        if (p < STRIDE) g_ell[d * STRIDE + p] = s;
    }
}

__global__ void make_scale_kernel() {
    int i = blockIdx.x * blockDim.x + threadIdx.x;
    if (i < NN) {
        int co = g_cnt_out[i]; if (co < 1) co = 1;
        int ci = g_fill[i];    if (ci < 1) ci = 1;
        g_dego[i] = rsqrtf((float)co);
        g_degi[i] = rsqrtf((float)ci);
    }
}

// ---------------- GEMM: g_tmp = (A @ W) [* dego[row] if apply_scale] ----------------
// 512 threads, tile 128x128, each thread 4 rows x 8 cols.
// rg = t>>4 : rows 4*rg .. 4*rg+3
// cg = t&15 : float4 col-groups cg and cg+16
// Per warp per k: 2 LDS.128 of W (lanes 0-15 hit 16 consecutive float4s,
// conflict-free, upper half-warp broadcast) = 8 wavefronts + 4 broadcast scalar
// A loads = 12 wavefronts vs 32 FFMA warp-instr -> FFMA-bound.
__global__ __launch_bounds__(512) void gemm128_kernel(
    const float* __restrict__ A_ext, int use_gh,
    const float* __restrict__ W, int n, int apply_scale)
{
    extern __shared__ float sm[];
    float* sW = sm;                 // 128*128 floats (64 KB)
    float* sA = sm + 128 * 128;     // 128*132 floats (67.6 KB)

    const float* A = use_gh ? g_h : A_ext;
    int t = threadIdx.x;
    int row0 = blockIdx.x * 128;

    // load W: 4096 float4, 8 per thread, coalesced
    for (int i = t; i < 128 * 32; i += 512)
        ((float4*)sW)[i] = ((const float4*)W)[i];

    // load A tile as float4 into padded rows (33 float4 per row = 132 floats)
    for (int i = t; i < 128 * 32; i += 512) {
        int r = i >> 5, c4 = i & 31;
        int row = row0 + r;
        float4 v = make_float4(0.f, 0.f, 0.f, 0.f);
        if (row < n) v = ((const float4*)A)[(size_t)row * 32 + c4];
        ((float4*)sA)[r * 33 + c4] = v;
    }
    __syncthreads();

    int rg = t >> 4;        // 0..31 : rows 4*rg .. 4*rg+3
    int cg = t & 15;        // float4 col-groups cg, cg+16
    const float4* sW4 = (const float4*)sW;
    const float* sArow = sA + 4 * rg * 132;

    float4 acc[4][2];
    #pragma unroll
    for (int r = 0; r < 4; ++r) {
        acc[r][0] = make_float4(0.f, 0.f, 0.f, 0.f);
        acc[r][1] = make_float4(0.f, 0.f, 0.f, 0.f);
    }

    #pragma unroll 4
    for (int k = 0; k < 128; ++k) {
        float4 w0 = sW4[k * 32 + cg     ];
        float4 w1 = sW4[k * 32 + cg + 16];
        float a0 = sArow[          k];
        float a1 = sArow[    132 + k];
        float a2 = sArow[2 * 132 + k];
        float a3 = sArow[3 * 132 + k];
        acc[0][0].x = fmaf(a0, w0.x, acc[0][0].x);
        acc[0][0].y = fmaf(a0, w0.y, acc[0][0].y);
        acc[0][0].z = fmaf(a0, w0.z, acc[0][0].z);
        acc[0][0].w = fmaf(a0, w0.w, acc[0][0].w);
        acc[0][1].x = fmaf(a0, w1.x, acc[0][1].x);
        acc[0][1].y = fmaf(a0, w1.y, acc[0][1].y);
        acc[0][1].z = fmaf(a0, w1.z, acc[0][1].z);
        acc[0][1].w = fmaf(a0, w1.w, acc[0][1].w);
        acc[1][0].x = fmaf(a1, w0.x, acc[1][0].x);
        acc[1][0].y = fmaf(a1, w0.y, acc[1][0].y);
        acc[1][0].z = fmaf(a1, w0.z, acc[1][0].z);
        acc[1][0].w = fmaf(a1, w0.w, acc[1][0].w);
        acc[1][1].x = fmaf(a1, w1.x, acc[1][1].x);
        acc[1][1].y = fmaf(a1, w1.y, acc[1][1].y);
        acc[1][1].z = fmaf(a1, w1.z, acc[1][1].z);
        acc[1][1].w = fmaf(a1, w1.w, acc[1][1].w);
        acc[2][0].x = fmaf(a2, w0.x, acc[2][0].x);
        acc[2][0].y = fmaf(a2, w0.y, acc[2][0].y);
        acc[2][0].z = fmaf(a2, w0.z, acc[2][0].z);
        acc[2][0].w = fmaf(a2, w0.w, acc[2][0].w);
        acc[2][1].x = fmaf(a2, w1.x, acc[2][1].x);
        acc[2][1].y = fmaf(a2, w1.y, acc[2][1].y);
        acc[2][1].z = fmaf(a2, w1.z, acc[2][1].z);
        acc[2][1].w = fmaf(a2, w1.w, acc[2][1].w);
        acc[3][0].x = fmaf(a3, w0.x, acc[3][0].x);
        acc[3][0].y = fmaf(a3, w0.y, acc[3][0].y);
        acc[3][0].z = fmaf(a3, w0.z, acc[3][0].z);
        acc[3][0].w = fmaf(a3, w0.w, acc[3][0].w);
        acc[3][1].x = fmaf(a3, w1.x, acc[3][1].x);
        acc[3][1].y = fmaf(a3, w1.y, acc[3][1].y);
        acc[3][1].z = fmaf(a3, w1.z, acc[3][1].z);
        acc[3][1].w = fmaf(a3, w1.w, acc[3][1].w);
    }

    #pragma unroll
    for (int r = 0; r < 4; ++r) {
        int row = row0 + 4 * rg + r;
        if (row < n) {
            float s = apply_scale ? g_dego[row] : 1.0f;
            float4* o = (float4*)(g_tmp + (size_t)row * 128);
            o[cg     ] = make_float4(acc[r][0].x * s, acc[r][0].y * s,
                                     acc[r][0].z * s, acc[r][0].w * s);
            o[cg + 16] = make_float4(acc[r][1].x * s, acc[r][1].y * s,
                                     acc[r][1].z * s, acc[r][1].w * s);
        }
    }
}

// ---------------- gather-aggregate + finalize ----------------
// one warp per dst node; src_scale=1 applies dego[s] per edge (layer 1)
__global__ __launch_bounds__(256) void gather_kernel(
    const float* __restrict__ b, float* __restrict__ dst_ext, int src_scale)
{
    int v = blockIdx.x * 8 + (threadIdx.x >> 5);
    if (v >= NN) return;
    int lane = threadIdx.x & 31;

    int cnt = g_fill[v];
    if (cnt > STRIDE) cnt = STRIDE;
    const int* lst = g_ell + (size_t)v * STRIDE;

    float4 acc = make_float4(0.f, 0.f, 0.f, 0.f);
    if (src_scale) {
        int j = 0;
        for (; j + 1 < cnt; j += 2) {
            int s0 = lst[j], s1 = lst[j + 1];
            float c0 = g_dego[s0], c1 = g_dego[s1];
            float4 a0 = ((const float4*)(g_tmp + (size_t)s0 * 128))[lane];
            float4 a1 = ((const float4*)(g_tmp + (size_t)s1 * 128))[lane];
            acc.x = fmaf(a0.x, c0, fmaf(a1.x, c1, acc.x));
            acc.y = fmaf(a0.y, c0, fmaf(a1.y, c1, acc.y));
            acc.z = fmaf(a0.z, c0, fmaf(a1.z, c1, acc.z));
            acc.w = fmaf(a0.w, c0, fmaf(a1.w, c1, acc.w));
        }
        for (; j < cnt; ++j) {
            int s = lst[j];
            float c = g_dego[s];
            float4 a = ((const float4*)(g_tmp + (size_t)s * 128))[lane];
            acc.x = fmaf(a.x, c, acc.x); acc.y = fmaf(a.y, c, acc.y);
            acc.z = fmaf(a.z, c, acc.z); acc.w = fmaf(a.w, c, acc.w);
        }
    } else {
        int j = 0;
        for (; j + 3 < cnt; j += 4) {
            int s0 = lst[j], s1 = lst[j + 1], s2 = lst[j + 2], s3 = lst[j + 3];
            float4 a0 = ((const float4*)(g_tmp + (size_t)s0 * 128))[lane];
            float4 a1 = ((const float4*)(g_tmp + (size_t)s1 * 128))[lane];
            float4 a2 = ((const float4*)(g_tmp + (size_t)s2 * 128))[lane];
            float4 a3 = ((const float4*)(g_tmp + (size_t)s3 * 128))[lane];
            acc.x += a0.x + a1.x + a2.x + a3.x;
            acc.y += a0.y + a1.y + a2.y + a3.y;
            acc.z += a0.z + a1.z + a2.z + a3.z;
            acc.w += a0.w + a1.w + a2.w + a3.w;
        }
        for (; j < cnt; ++j) {
            int s = lst[j];
            float4 a = ((const float4*)(g_tmp + (size_t)s * 128))[lane];
            acc.x += a.x; acc.y += a.y; acc.z += a.z; acc.w += a.w;
        }
    }

    float sc = g_degi[v];
    float4 bb = ((const float4*)b)[lane];
    float4 o;
    o.x = fmaf(acc.x, sc, bb.x); o.x = o.x > 0.f ? o.x : 0.f;
    o.y = fmaf(acc.y, sc, bb.y); o.y = o.y > 0.f ? o.y : 0.f;
    o.z = fmaf(acc.z, sc, bb.z); o.z = o.z > 0.f ? o.z : 0.f;
    o.w = fmaf(acc.w, sc, bb.w); o.w = o.w > 0.f ? o.w : 0.f;

    float* dst = dst_ext ? dst_ext : g_h;
    ((float4*)(dst + (size_t)v * 128))[lane] = o;
}

// ---------------- edge classifier ----------------
__global__ __launch_bounds__(256) void edge_cls_kernel(
    const float* __restrict__ h,
    const int* __restrict__ cs, const int* __restrict__ cd,
    const float* __restrict__ Wc, const float* __restrict__ bc,
    float* __restrict__ out)
{
    int w = threadIdx.x >> 5, lane = threadIdx.x & 31;
    int i = blockIdx.x * 8 + w;
    if (i >= ECC) return;

    int k0 = lane * 4;
    float w0s[4], w1s[4], w0d[4], w1d[4];
    #pragma unroll
    for (int j = 0; j < 4; ++j) {
        w0s[j] = __ldg(&Wc[(k0 + j) * 2    ]);
        w1s[j] = __ldg(&Wc[(k0 + j) * 2 + 1]);
        w0d[j] = __ldg(&Wc[(128 + k0 + j) * 2    ]);
        w1d[j] = __ldg(&Wc[(128 + k0 + j) * 2 + 1]);
    }

    int s = __ldg(&cs[i]);
    int d = __ldg(&cd[i]);
    float4 a = ((const float4*)(h + (size_t)s * 128))[lane];
    float4 b = ((const float4*)(h + (size_t)d * 128))[lane];

    float l0 = a.x * w0s[0] + a.y * w0s[1] + a.z * w0s[2] + a.w * w0s[3]
             + b.x * w0d[0] + b.y * w0d[1] + b.z * w0d[2] + b.w * w0d[3];
    float l1 = a.x * w1s[0] + a.y * w1s[1] + a.z * w1s[2] + a.w * w1s[3]
             + b.x * w1d[0] + b.y * w1d[1] + b.z * w1d[2] + b.w * w1d[3];

    #pragma unroll
    for (int m = 16; m > 0; m >>= 1) {
        l0 += __shfl_xor_sync(0xffffffffu, l0, m);
        l1 += __shfl_xor_sync(0xffffffffu, l1, m);
    }

    if (lane == 0) {
        float z0 = l0 + __ldg(&bc[0]);
        float z1 = l1 + __ldg(&bc[1]);
        out[(size_t)i * 2    ] = 1.0f / (1.0f + expf(-z0));
        out[(size_t)i * 2 + 1] = 1.0f / (1.0f + expf(-z1));
    }
}

// ---------------- launch ----------------
extern "C" void kernel_launch(void* const* d_in, const int* in_sizes, int n_in,
                              void* d_out, int out_size)
{
    const float* feat = (const float*)d_in[0];
    const int*   gsrc = (const int*)  d_in[1];
    const int*   gdst = (const int*)  d_in[2];
    const int*   csrc = (const int*)  d_in[3];
    const int*   cdst = (const int*)  d_in[4];
    const float* W1   = (const float*)d_in[5];
    const float* b1   = (const float*)d_in[6];
    const float* W2   = (const float*)d_in[7];
    const float* b2   = (const float*)d_in[8];
    const float* Wc   = (const float*)d_in[9];
    const float* bc   = (const float*)d_in[10];
    float* out = (float*)d_out;

    const int GEMM_SMEM = (128 * 128 + 128 * 132) * 4;  // 133,120 B
    static int attr_done = 0;
    if (!attr_done) {
        cudaFuncSetAttribute(gemm128_kernel,
                             cudaFuncAttributeMaxDynamicSharedMemorySize, GEMM_SMEM);
        attr_done = 1;
    }

    // graph build
    zero_cnt_kernel<<<(NN + 255) / 256, 256>>>();                       // launch 0
    build_graph_kernel<<<(EE + 255) / 256, 256>>>(gsrc, gdst);          // launch 1
    make_scale_kernel<<<(NN + 255) / 256, 256>>>();                     // launch 2

    // GEMM1 (unscaled; dego applied per-edge in gather1) — launch index 3 for ncu
    gemm128_kernel<<<(NN + 127) / 128, 512, GEMM_SMEM>>>(feat, 0, W1, NN, 0);    // launch 3

    // layer 1 aggregate (applies dego[src] per edge) -> g_h
    gather_kernel<<<(NN + 7) / 8, 256>>>(b1, nullptr, 1);               // launch 4

    // layer 2
    gemm128_kernel<<<(NN + 127) / 128, 512, GEMM_SMEM>>>(nullptr, 1, W2, NN, 1); // launch 5
    gather_kernel<<<(NN + 7) / 8, 256>>>(b2, out, 0);                   // launch 6

    // edge classifier
    edge_cls_kernel<<<(ECC + 7) / 8, 256>>>(out, csrc, cdst, Wc, bc,
                                            out + (size_t)NN * HH);     // launch 7
}

// round 11
// speedup vs baseline: 2.1719x; 1.0346x over previous
#include <cuda_runtime.h>
#include <math.h>

#define NN 50000
#define HH 128
#define EE 800000
#define ECC 200000
#define STRIDE 64           // max in-degree bucket (Poisson(16): P(>64) ~ 1e-20)

// ---------------- scratch (no allocations allowed) ----------------
__device__ float g_tmp[NN * HH];       // GEMM output (message to send)
__device__ float g_h[NN * HH];         // hidden after layer 1
__device__ float g_dego[NN];           // deg_out^{-1/2}
__device__ float g_degi[NN];           // deg_in^{-1/2}
__device__ int   g_cnt_out[NN];        // int out-degree
__device__ int   g_fill[NN];           // ELL fill cursor == in-degree
__device__ int   g_ell[NN * STRIDE];   // per-dst src lists, fixed stride

// ---------------- degree / ELL kernels ----------------
__global__ void zero_cnt_kernel() {
    int i = blockIdx.x * blockDim.x + threadIdx.x;
    if (i < NN) { g_cnt_out[i] = 0; g_fill[i] = 0; }
}

// single edge pass: out-degree count + ELL bucket fill (fill cursor = in-degree)
__global__ void build_graph_kernel(const int* __restrict__ src, const int* __restrict__ dst) {
    int i = blockIdx.x * blockDim.x + threadIdx.x;
    if (i < EE) {
        int s = src[i], d = dst[i];
        atomicAdd(&g_cnt_out[s], 1);
        int p = atomicAdd(&g_fill[d], 1);
        if (p < STRIDE) g_ell[d * STRIDE + p] = s;
    }
}

__global__ void make_scale_kernel() {
    int i = blockIdx.x * blockDim.x + threadIdx.x;
    if (i < NN) {
        int co = g_cnt_out[i]; if (co < 1) co = 1;
        int ci = g_fill[i];    if (ci < 1) ci = 1;
        g_dego[i] = rsqrtf((float)co);
        g_degi[i] = rsqrtf((float)ci);
    }
}

// ---------------- GEMM: g_tmp = (A @ W) [* dego[row] if apply_scale] ----------------
// 512 threads, tile 128 rows x 128 cols, K staged in TWO chunks of 64 so smem
// fits 2 CTAs/SM (67.6 KB): sW chunk 64x128 (32 KB) + sA chunk 128x68 (34.8 KB).
// Thread map: rg=t>>4 (4 rows), cg=t&15 (float4 col-groups cg, cg+16).
// W LDS.128: half-warp reads 16 consecutive float4s, upper half broadcasts -> 2 wf.
// A scalar reads: rg/rg+1 differ by 1088 B -> distinct banks.
__global__ __launch_bounds__(512, 2) void gemm128_kernel(
    const float* __restrict__ A_ext, int use_gh,
    const float* __restrict__ W, int n, int apply_scale)
{
    extern __shared__ float sm[];
    float* sW = sm;                 // 64*128 floats (chunk)
    float* sA = sm + 64 * 128;      // 128*68 floats (chunk, 64 cols + 4 pad)

    const float* A = use_gh ? g_h : A_ext;
    int t = threadIdx.x;
    int row0 = blockIdx.x * 128;

    int rg = t >> 4;        // 0..31 : rows 4*rg .. 4*rg+3
    int cg = t & 15;        // float4 col-groups cg, cg+16
    const float4* sW4 = (const float4*)sW;

    float4 acc[4][2];
    #pragma unroll
    for (int r = 0; r < 4; ++r) {
        acc[r][0] = make_float4(0.f, 0.f, 0.f, 0.f);
        acc[r][1] = make_float4(0.f, 0.f, 0.f, 0.f);
    }

    #pragma unroll 1
    for (int c = 0; c < 2; ++c) {
        if (c) __syncthreads();     // protect smem reuse across chunks

        // load W chunk: k rows c*64 .. c*64+63, 32 float4 per row
        for (int i = t; i < 64 * 32; i += 512)
            ((float4*)sW)[i] = ((const float4*)W)[c * 64 * 32 + i];

        // load A chunk: 128 rows x 16 float4 (cols c*64..c*64+63), pitch 17 float4
        for (int i = t; i < 128 * 16; i += 512) {
            int r = i >> 4, c4 = i & 15;
            int row = row0 + r;
            float4 v = make_float4(0.f, 0.f, 0.f, 0.f);
            if (row < n) v = ((const float4*)A)[(size_t)row * 32 + c * 16 + c4];
            ((float4*)sA)[r * 17 + c4] = v;
        }
        __syncthreads();

        const float* sArow = sA + 4 * rg * 68;
        #pragma unroll 4
        for (int k = 0; k < 64; ++k) {
            float4 w0 = sW4[k * 32 + cg     ];
            float4 w1 = sW4[k * 32 + cg + 16];
            float a0 = sArow[          k];
            float a1 = sArow[     68 + k];
            float a2 = sArow[2 *  68 + k];
            float a3 = sArow[3 *  68 + k];
            acc[0][0].x = fmaf(a0, w0.x, acc[0][0].x);
            acc[0][0].y = fmaf(a0, w0.y, acc[0][0].y);
            acc[0][0].z = fmaf(a0, w0.z, acc[0][0].z);
            acc[0][0].w = fmaf(a0, w0.w, acc[0][0].w);
            acc[0][1].x = fmaf(a0, w1.x, acc[0][1].x);
            acc[0][1].y = fmaf(a0, w1.y, acc[0][1].y);
            acc[0][1].z = fmaf(a0, w1.z, acc[0][1].z);
            acc[0][1].w = fmaf(a0, w1.w, acc[0][1].w);
            acc[1][0].x = fmaf(a1, w0.x, acc[1][0].x);
            acc[1][0].y = fmaf(a1, w0.y, acc[1][0].y);
            acc[1][0].z = fmaf(a1, w0.z, acc[1][0].z);
            acc[1][0].w = fmaf(a1, w0.w, acc[1][0].w);
            acc[1][1].x = fmaf(a1, w1.x, acc[1][1].x);
            acc[1][1].y = fmaf(a1, w1.y, acc[1][1].y);
            acc[1][1].z = fmaf(a1, w1.z, acc[1][1].z);
            acc[1][1].w = fmaf(a1, w1.w, acc[1][1].w);
            acc[2][0].x = fmaf(a2, w0.x, acc[2][0].x);
            acc[2][0].y = fmaf(a2, w0.y, acc[2][0].y);
            acc[2][0].z = fmaf(a2, w0.z, acc[2][0].z);
            acc[2][0].w = fmaf(a2, w0.w, acc[2][0].w);
            acc[2][1].x = fmaf(a2, w1.x, acc[2][1].x);
            acc[2][1].y = fmaf(a2, w1.y, acc[2][1].y);
            acc[2][1].z = fmaf(a2, w1.z, acc[2][1].z);
            acc[2][1].w = fmaf(a2, w1.w, acc[2][1].w);
            acc[3][0].x = fmaf(a3, w0.x, acc[3][0].x);
            acc[3][0].y = fmaf(a3, w0.y, acc[3][0].y);
            acc[3][0].z = fmaf(a3, w0.z, acc[3][0].z);
            acc[3][0].w = fmaf(a3, w0.w, acc[3][0].w);
            acc[3][1].x = fmaf(a3, w1.x, acc[3][1].x);
            acc[3][1].y = fmaf(a3, w1.y, acc[3][1].y);
            acc[3][1].z = fmaf(a3, w1.z, acc[3][1].z);
            acc[3][1].w = fmaf(a3, w1.w, acc[3][1].w);
        }
    }

    #pragma unroll
    for (int r = 0; r < 4; ++r) {
        int row = row0 + 4 * rg + r;
        if (row < n) {
            float s = apply_scale ? g_dego[row] : 1.0f;
            float4* o = (float4*)(g_tmp + (size_t)row * 128);
            o[cg     ] = make_float4(acc[r][0].x * s, acc[r][0].y * s,
                                     acc[r][0].z * s, acc[r][0].w * s);
            o[cg + 16] = make_float4(acc[r][1].x * s, acc[r][1].y * s,
                                     acc[r][1].z * s, acc[r][1].w * s);
        }
    }
}

// ---------------- gather-aggregate + finalize ----------------
// one warp per dst node; src_scale=1 applies dego[s] per edge (layer 1)
__global__ __launch_bounds__(256) void gather_kernel(
    const float* __restrict__ b, float* __restrict__ dst_ext, int src_scale)
{
    int v = blockIdx.x * 8 + (threadIdx.x >> 5);
    if (v >= NN) return;
    int lane = threadIdx.x & 31;

    int cnt = g_fill[v];
    if (cnt > STRIDE) cnt = STRIDE;
    const int* lst = g_ell + (size_t)v * STRIDE;

    float4 acc = make_float4(0.f, 0.f, 0.f, 0.f);
    if (src_scale) {
        int j = 0;
        for (; j + 1 < cnt; j += 2) {
            int s0 = lst[j], s1 = lst[j + 1];
            float c0 = g_dego[s0], c1 = g_dego[s1];
            float4 a0 = ((const float4*)(g_tmp + (size_t)s0 * 128))[lane];
            float4 a1 = ((const float4*)(g_tmp + (size_t)s1 * 128))[lane];
            acc.x = fmaf(a0.x, c0, fmaf(a1.x, c1, acc.x));
            acc.y = fmaf(a0.y, c0, fmaf(a1.y, c1, acc.y));
            acc.z = fmaf(a0.z, c0, fmaf(a1.z, c1, acc.z));
            acc.w = fmaf(a0.w, c0, fmaf(a1.w, c1, acc.w));
        }
        for (; j < cnt; ++j) {
            int s = lst[j];
            float c = g_dego[s];
            float4 a = ((const float4*)(g_tmp + (size_t)s * 128))[lane];
            acc.x = fmaf(a.x, c, acc.x); acc.y = fmaf(a.y, c, acc.y);
            acc.z = fmaf(a.z, c, acc.z); acc.w = fmaf(a.w, c, acc.w);
        }
    } else {
        int j = 0;
        for (; j + 3 < cnt; j += 4) {
            int s0 = lst[j], s1 = lst[j + 1], s2 = lst[j + 2], s3 = lst[j + 3];
            float4 a0 = ((const float4*)(g_tmp + (size_t)s0 * 128))[lane];
            float4 a1 = ((const float4*)(g_tmp + (size_t)s1 * 128))[lane];
            float4 a2 = ((const float4*)(g_tmp + (size_t)s2 * 128))[lane];
            float4 a3 = ((const float4*)(g_tmp + (size_t)s3 * 128))[lane];
            acc.x += a0.x + a1.x + a2.x + a3.x;
            acc.y += a0.y + a1.y + a2.y + a3.y;
            acc.z += a0.z + a1.z + a2.z + a3.z;
            acc.w += a0.w + a1.w + a2.w + a3.w;
        }
        for (; j < cnt; ++j) {
            int s = lst[j];
            float4 a = ((const float4*)(g_tmp + (size_t)s * 128))[lane];
            acc.x += a.x; acc.y += a.y; acc.z += a.z; acc.w += a.w;
        }
    }

    float sc = g_degi[v];
    float4 bb = ((const float4*)b)[lane];
    float4 o;
    o.x = fmaf(acc.x, sc, bb.x); o.x = o.x > 0.f ? o.x : 0.f;
    o.y = fmaf(acc.y, sc, bb.y); o.y = o.y > 0.f ? o.y : 0.f;
    o.z = fmaf(acc.z, sc, bb.z); o.z = o.z > 0.f ? o.z : 0.f;
    o.w = fmaf(acc.w, sc, bb.w); o.w = o.w > 0.f ? o.w : 0.f;

    float* dst = dst_ext ? dst_ext : g_h;
    ((float4*)(dst + (size_t)v * 128))[lane] = o;
}

// ---------------- edge classifier ----------------
__global__ __launch_bounds__(256) void edge_cls_kernel(
    const float* __restrict__ h,
    const int* __restrict__ cs, const int* __restrict__ cd,
    const float* __restrict__ Wc, const float* __restrict__ bc,
    float* __restrict__ out)
{
    int w = threadIdx.x >> 5, lane = threadIdx.x & 31;
    int i = blockIdx.x * 8 + w;
    if (i >= ECC) return;

    int k0 = lane * 4;
    float w0s[4], w1s[4], w0d[4], w1d[4];
    #pragma unroll
    for (int j = 0; j < 4; ++j) {
        w0s[j] = __ldg(&Wc[(k0 + j) * 2    ]);
        w1s[j] = __ldg(&Wc[(k0 + j) * 2 + 1]);
        w0d[j] = __ldg(&Wc[(128 + k0 + j) * 2    ]);
        w1d[j] = __ldg(&Wc[(128 + k0 + j) * 2 + 1]);
    }

    int s = __ldg(&cs[i]);
    int d = __ldg(&cd[i]);
    float4 a = ((const float4*)(h + (size_t)s * 128))[lane];
    float4 b = ((const float4*)(h + (size_t)d * 128))[lane];

    float l0 = a.x * w0s[0] + a.y * w0s[1] + a.z * w0s[2] + a.w * w0s[3]
             + b.x * w0d[0] + b.y * w0d[1] + b.z * w0d[2] + b.w * w0d[3];
    float l1 = a.x * w1s[0] + a.y * w1s[1] + a.z * w1s[2] + a.w * w1s[3]
             + b.x * w1d[0] + b.y * w1d[1] + b.z * w1d[2] + b.w * w1d[3];

    #pragma unroll
    for (int m = 16; m > 0; m >>= 1) {
        l0 += __shfl_xor_sync(0xffffffffu, l0, m);
        l1 += __shfl_xor_sync(0xffffffffu, l1, m);
    }

    if (lane == 0) {
        float z0 = l0 + __ldg(&bc[0]);
        float z1 = l1 + __ldg(&bc[1]);
        out[(size_t)i * 2    ] = 1.0f / (1.0f + expf(-z0));
        out[(size_t)i * 2 + 1] = 1.0f / (1.0f + expf(-z1));
    }
}

// ---------------- launch ----------------
extern "C" void kernel_launch(void* const* d_in, const int* in_sizes, int n_in,
                              void* d_out, int out_size)
{
    const float* feat = (const float*)d_in[0];
    const int*   gsrc = (const int*)  d_in[1];
    const int*   gdst = (const int*)  d_in[2];
    const int*   csrc = (const int*)  d_in[3];
    const int*   cdst = (const int*)  d_in[4];
    const float* W1   = (const float*)d_in[5];
    const float* b1   = (const float*)d_in[6];
    const float* W2   = (const float*)d_in[7];
    const float* b2   = (const float*)d_in[8];
    const float* Wc   = (const float*)d_in[9];
    const float* bc   = (const float*)d_in[10];
    float* out = (float*)d_out;

    const int GEMM_SMEM = (64 * 128 + 128 * 68) * 4;  // 67,584 B -> 2 CTAs/SM
    static cudaStream_t sB;
    static cudaEvent_t evA, evB;
    static int init_done = 0;
    if (!init_done) {
        // first call is the uncaptured correctness run: safe to create resources
        cudaFuncSetAttribute(gemm128_kernel,
                             cudaFuncAttributeMaxDynamicSharedMemorySize, GEMM_SMEM);
        cudaStreamCreateWithFlags(&sB, cudaStreamNonBlocking);
        cudaEventCreateWithFlags(&evA, cudaEventDisableTiming);
        cudaEventCreateWithFlags(&evB, cudaEventDisableTiming);
        init_done = 1;
    }

    // fork: GEMM1 (independent of graph build; dego applied per-edge in gather1)
    cudaEventRecord(evA, 0);
    cudaStreamWaitEvent(sB, evA, 0);

    // default stream: graph build chain
    zero_cnt_kernel<<<(NN + 255) / 256, 256>>>();                       // launch 0
    build_graph_kernel<<<(EE + 255) / 256, 256>>>(gsrc, gdst);          // launch 1
    make_scale_kernel<<<(NN + 255) / 256, 256>>>();                     // launch 2

    // stream B: GEMM1 — 4th launch for ncu capture
    gemm128_kernel<<<(NN + 127) / 128, 512, GEMM_SMEM, sB>>>(feat, 0, W1, NN, 0); // launch 3

    // join
    cudaEventRecord(evB, sB);
    cudaStreamWaitEvent(0, evB, 0);

    // layer 1 aggregate (applies dego[src] per edge) -> g_h
    gather_kernel<<<(NN + 7) / 8, 256>>>(b1, nullptr, 1);               // launch 4

    // layer 2
    gemm128_kernel<<<(NN + 127) / 128, 512, GEMM_SMEM>>>(nullptr, 1, W2, NN, 1); // launch 5
    gather_kernel<<<(NN + 7) / 8, 256>>>(b2, out, 0);                   // launch 6

    // edge classifier
    edge_cls_kernel<<<(ECC + 7) / 8, 256>>>(out, csrc, cdst, Wc, bc,
                                            out + (size_t)NN * HH);     // launch 7
}

// round 13
// speedup vs baseline: 2.2550x; 1.0382x over previous
#include <cuda_runtime.h>
#include <cuda_fp16.h>
#include <math.h>

#define NN 50000
#define HH 128
#define EE 800000
#define ECC 200000
#define STRIDE 64           // max in-degree bucket (Poisson(16): P(>64) ~ 1e-20)

// ---------------- scratch (no allocations allowed) ----------------
__device__ __half g_tmp[NN * HH];      // GEMM output messages (fp16, halves gather traffic)
__device__ float  g_h[NN * HH];        // hidden after layer 1 (fp32)
__device__ float  g_dego[NN];          // deg_out^{-1/2}
__device__ float  g_degi[NN];          // deg_in^{-1/2}
__device__ int    g_cnt_out[NN];       // int out-degree
__device__ int    g_fill[NN];          // ELL fill cursor == in-degree
__device__ int    g_ell[NN * STRIDE];  // per-dst src lists, fixed stride

// ---------------- degree / ELL kernels ----------------
__global__ void zero_cnt_kernel() {
    int i = blockIdx.x * blockDim.x + threadIdx.x;
    if (i < NN) { g_cnt_out[i] = 0; g_fill[i] = 0; }
}

__global__ void build_graph_kernel(const int* __restrict__ src, const int* __restrict__ dst) {
    int i = blockIdx.x * blockDim.x + threadIdx.x;
    if (i < EE) {
        int s = src[i], d = dst[i];
        atomicAdd(&g_cnt_out[s], 1);
        int p = atomicAdd(&g_fill[d], 1);
        if (p < STRIDE) g_ell[d * STRIDE + p] = s;
    }
}

__global__ void make_scale_kernel() {
    int i = blockIdx.x * blockDim.x + threadIdx.x;
    if (i < NN) {
        int co = g_cnt_out[i]; if (co < 1) co = 1;
        int ci = g_fill[i];    if (ci < 1) ci = 1;
        g_dego[i] = rsqrtf((float)co);
        g_degi[i] = rsqrtf((float)ci);
    }
}

// ---------------- GEMM: g_tmp = fp16( (A @ W) [* dego[row]] ) ----------------
// 512 threads, tile 128x128, K in two 64-chunks (67.6 KB smem -> 2 CTAs/SM).
__global__ __launch_bounds__(512, 2) void gemm128_kernel(
    const float* __restrict__ A_ext, int use_gh,
    const float* __restrict__ W, int n, int apply_scale)
{
    extern __shared__ float sm[];
    float* sW = sm;                 // 64*128 floats (chunk)
    float* sA = sm + 64 * 128;      // 128*68 floats (chunk, 64 cols + 4 pad)

    const float* A = use_gh ? g_h : A_ext;
    int t = threadIdx.x;
    int row0 = blockIdx.x * 128;

    int rg = t >> 4;        // 0..31 : rows 4*rg .. 4*rg+3
    int cg = t & 15;        // float4 col-groups cg, cg+16
    const float4* sW4 = (const float4*)sW;

    float4 acc[4][2];
    #pragma unroll
    for (int r = 0; r < 4; ++r) {
        acc[r][0] = make_float4(0.f, 0.f, 0.f, 0.f);
        acc[r][1] = make_float4(0.f, 0.f, 0.f, 0.f);
    }

    #pragma unroll 1
    for (int c = 0; c < 2; ++c) {
        if (c) __syncthreads();

        for (int i = t; i < 64 * 32; i += 512)
            ((float4*)sW)[i] = ((const float4*)W)[c * 64 * 32 + i];

        for (int i = t; i < 128 * 16; i += 512) {
            int r = i >> 4, c4 = i & 15;
            int row = row0 + r;
            float4 v = make_float4(0.f, 0.f, 0.f, 0.f);
            if (row < n) v = ((const float4*)A)[(size_t)row * 32 + c * 16 + c4];
            ((float4*)sA)[r * 17 + c4] = v;
        }
        __syncthreads();

        const float* sArow = sA + 4 * rg * 68;
        #pragma unroll 4
        for (int k = 0; k < 64; ++k) {
            float4 w0 = sW4[k * 32 + cg     ];
            float4 w1 = sW4[k * 32 + cg + 16];
            float a0 = sArow[          k];
            float a1 = sArow[     68 + k];
            float a2 = sArow[2 *  68 + k];
            float a3 = sArow[3 *  68 + k];
            acc[0][0].x = fmaf(a0, w0.x, acc[0][0].x);
            acc[0][0].y = fmaf(a0, w0.y, acc[0][0].y);
            acc[0][0].z = fmaf(a0, w0.z, acc[0][0].z);
            acc[0][0].w = fmaf(a0, w0.w, acc[0][0].w);
            acc[0][1].x = fmaf(a0, w1.x, acc[0][1].x);
            acc[0][1].y = fmaf(a0, w1.y, acc[0][1].y);
            acc[0][1].z = fmaf(a0, w1.z, acc[0][1].z);
            acc[0][1].w = fmaf(a0, w1.w, acc[0][1].w);
            acc[1][0].x = fmaf(a1, w0.x, acc[1][0].x);
            acc[1][0].y = fmaf(a1, w0.y, acc[1][0].y);
            acc[1][0].z = fmaf(a1, w0.z, acc[1][0].z);
            acc[1][0].w = fmaf(a1, w0.w, acc[1][0].w);
            acc[1][1].x = fmaf(a1, w1.x, acc[1][1].x);
            acc[1][1].y = fmaf(a1, w1.y, acc[1][1].y);
            acc[1][1].z = fmaf(a1, w1.z, acc[1][1].z);
            acc[1][1].w = fmaf(a1, w1.w, acc[1][1].w);
            acc[2][0].x = fmaf(a2, w0.x, acc[2][0].x);
            acc[2][0].y = fmaf(a2, w0.y, acc[2][0].y);
            acc[2][0].z = fmaf(a2, w0.z, acc[2][0].z);
            acc[2][0].w = fmaf(a2, w0.w, acc[2][0].w);
            acc[2][1].x = fmaf(a2, w1.x, acc[2][1].x);
            acc[2][1].y = fmaf(a2, w1.y, acc[2][1].y);
            acc[2][1].z = fmaf(a2, w1.z, acc[2][1].z);
            acc[2][1].w = fmaf(a2, w1.w, acc[2][1].w);
            acc[3][0].x = fmaf(a3, w0.x, acc[3][0].x);
            acc[3][0].y = fmaf(a3, w0.y, acc[3][0].y);
            acc[3][0].z = fmaf(a3, w0.z, acc[3][0].z);
            acc[3][0].w = fmaf(a3, w0.w, acc[3][0].w);
            acc[3][1].x = fmaf(a3, w1.x, acc[3][1].x);
            acc[3][1].y = fmaf(a3, w1.y, acc[3][1].y);
            acc[3][1].z = fmaf(a3, w1.z, acc[3][1].z);
            acc[3][1].w = fmaf(a3, w1.w, acc[3][1].w);
        }
    }

    #pragma unroll
    for (int r = 0; r < 4; ++r) {
        int row = row0 + 4 * rg + r;
        if (row < n) {
            float s = apply_scale ? g_dego[row] : 1.0f;
            uint2* o = (uint2*)(g_tmp + (size_t)row * 128);   // 8B = 4 fp16 cols
            __half2 p0 = __floats2half2_rn(acc[r][0].x * s, acc[r][0].y * s);
            __half2 p1 = __floats2half2_rn(acc[r][0].z * s, acc[r][0].w * s);
            __half2 p2 = __floats2half2_rn(acc[r][1].x * s, acc[r][1].y * s);
            __half2 p3 = __floats2half2_rn(acc[r][1].z * s, acc[r][1].w * s);
            uint2 u0, u1;
            u0.x = *reinterpret_cast<unsigned*>(&p0);
            u0.y = *reinterpret_cast<unsigned*>(&p1);
            u1.x = *reinterpret_cast<unsigned*>(&p2);
            u1.y = *reinterpret_cast<unsigned*>(&p3);
            o[cg     ] = u0;
            o[cg + 16] = u1;
        }
    }
}

// ---------------- gather-aggregate + finalize ----------------
// one warp per dst node; lane owns cols 4*lane..4*lane+3 (uint2 = 4 fp16).
__device__ __forceinline__ float4 ld_msg(int s, int lane) {
    uint2 v = ((const uint2*)(g_tmp + (size_t)s * 128))[lane];
    __half2 h01 = *reinterpret_cast<__half2*>(&v.x);
    __half2 h23 = *reinterpret_cast<__half2*>(&v.y);
    float2 f01 = __half22float2(h01);
    float2 f23 = __half22float2(h23);
    return make_float4(f01.x, f01.y, f23.x, f23.y);
}

__global__ __launch_bounds__(256) void gather_kernel(
    const float* __restrict__ b, float* __restrict__ dst_ext, int src_scale)
{
    int v = blockIdx.x * 8 + (threadIdx.x >> 5);
    if (v >= NN) return;
    int lane = threadIdx.x & 31;

    int cnt = g_fill[v];
    if (cnt > STRIDE) cnt = STRIDE;
    const int* lst = g_ell + (size_t)v * STRIDE;

    float4 acc = make_float4(0.f, 0.f, 0.f, 0.f);
    if (src_scale) {
        int j = 0;
        for (; j + 1 < cnt; j += 2) {
            int s0 = lst[j], s1 = lst[j + 1];
            float c0 = g_dego[s0], c1 = g_dego[s1];
            float4 a0 = ld_msg(s0, lane);
            float4 a1 = ld_msg(s1, lane);
            acc.x = fmaf(a0.x, c0, fmaf(a1.x, c1, acc.x));
            acc.y = fmaf(a0.y, c0, fmaf(a1.y, c1, acc.y));
            acc.z = fmaf(a0.z, c0, fmaf(a1.z, c1, acc.z));
            acc.w = fmaf(a0.w, c0, fmaf(a1.w, c1, acc.w));
        }
        for (; j < cnt; ++j) {
            int s = lst[j];
            float c = g_dego[s];
            float4 a = ld_msg(s, lane);
            acc.x = fmaf(a.x, c, acc.x); acc.y = fmaf(a.y, c, acc.y);
            acc.z = fmaf(a.z, c, acc.z); acc.w = fmaf(a.w, c, acc.w);
        }
    } else {
        int j = 0;
        for (; j + 3 < cnt; j += 4) {
            int s0 = lst[j], s1 = lst[j + 1], s2 = lst[j + 2], s3 = lst[j + 3];
            float4 a0 = ld_msg(s0, lane);
            float4 a1 = ld_msg(s1, lane);
            float4 a2 = ld_msg(s2, lane);
            float4 a3 = ld_msg(s3, lane);
            acc.x += a0.x + a1.x + a2.x + a3.x;
            acc.y += a0.y + a1.y + a2.y + a3.y;
            acc.z += a0.z + a1.z + a2.z + a3.z;
            acc.w += a0.w + a1.w + a2.w + a3.w;
        }
        for (; j < cnt; ++j) {
            float4 a = ld_msg(lst[j], lane);
            acc.x += a.x; acc.y += a.y; acc.z += a.z; acc.w += a.w;
        }
    }

    float sc = g_degi[v];
    float4 bb = ((const float4*)b)[lane];
    float4 o;
    o.x = fmaf(acc.x, sc, bb.x); o.x = o.x > 0.f ? o.x : 0.f;
    o.y = fmaf(acc.y, sc, bb.y); o.y = o.y > 0.f ? o.y : 0.f;
    o.z = fmaf(acc.z, sc, bb.z); o.z = o.z > 0.f ? o.z : 0.f;
    o.w = fmaf(acc.w, sc, bb.w); o.w = o.w > 0.f ? o.w : 0.f;

    float* dst = dst_ext ? dst_ext : g_h;
    ((float4*)(dst + (size_t)v * 128))[lane] = o;
}

// ---------------- edge classifier ----------------
__global__ __launch_bounds__(256) void edge_cls_kernel(
    const float* __restrict__ h,
    const int* __restrict__ cs, const int* __restrict__ cd,
    const float* __restrict__ Wc, const float* __restrict__ bc,
    float* __restrict__ out)
{
    int w = threadIdx.x >> 5, lane = threadIdx.x & 31;
    int i = blockIdx.x * 8 + w;
    if (i >= ECC) return;

    int k0 = lane * 4;
    float w0s[4], w1s[4], w0d[4], w1d[4];
    #pragma unroll
    for (int j = 0; j < 4; ++j) {
        w0s[j] = __ldg(&Wc[(k0 + j) * 2    ]);
        w1s[j] = __ldg(&Wc[(k0 + j) * 2 + 1]);
        w0d[j] = __ldg(&Wc[(128 + k0 + j) * 2    ]);
        w1d[j] = __ldg(&Wc[(128 + k0 + j) * 2 + 1]);
    }

    int s = __ldg(&cs[i]);
    int d = __ldg(&cd[i]);
    float4 a = ((const float4*)(h + (size_t)s * 128))[lane];
    float4 b = ((const float4*)(h + (size_t)d * 128))[lane];

    float l0 = a.x * w0s[0] + a.y * w0s[1] + a.z * w0s[2] + a.w * w0s[3]
             + b.x * w0d[0] + b.y * w0d[1] + b.z * w0d[2] + b.w * w0d[3];
    float l1 = a.x * w1s[0] + a.y * w1s[1] + a.z * w1s[2] + a.w * w1s[3]
             + b.x * w1d[0] + b.y * w1d[1] + b.z * w1d[2] + b.w * w1d[3];

    #pragma unroll
    for (int m = 16; m > 0; m >>= 1) {
        l0 += __shfl_xor_sync(0xffffffffu, l0, m);
        l1 += __shfl_xor_sync(0xffffffffu, l1, m);
    }

    if (lane == 0) {
        float z0 = l0 + __ldg(&bc[0]);
        float z1 = l1 + __ldg(&bc[1]);
        out[(size_t)i * 2    ] = 1.0f / (1.0f + expf(-z0));
        out[(size_t)i * 2 + 1] = 1.0f / (1.0f + expf(-z1));
    }
}

// ---------------- launch ----------------
extern "C" void kernel_launch(void* const* d_in, const int* in_sizes, int n_in,
                              void* d_out, int out_size)
{
    const float* feat = (const float*)d_in[0];
    const int*   gsrc = (const int*)  d_in[1];
    const int*   gdst = (const int*)  d_in[2];
    const int*   csrc = (const int*)  d_in[3];
    const int*   cdst = (const int*)  d_in[4];
    const float* W1   = (const float*)d_in[5];
    const float* b1   = (const float*)d_in[6];
    const float* W2   = (const float*)d_in[7];
    const float* b2   = (const float*)d_in[8];
    const float* Wc   = (const float*)d_in[9];
    const float* bc   = (const float*)d_in[10];
    float* out = (float*)d_out;

    const int GEMM_SMEM = (64 * 128 + 128 * 68) * 4;  // 67,584 B -> 2 CTAs/SM
    static cudaStream_t sB;
    static cudaEvent_t evA, evB;
    static int init_done = 0;
    if (!init_done) {
        cudaFuncSetAttribute(gemm128_kernel,
                             cudaFuncAttributeMaxDynamicSharedMemorySize, GEMM_SMEM);
        cudaStreamCreateWithFlags(&sB, cudaStreamNonBlocking);
        cudaEventCreateWithFlags(&evA, cudaEventDisableTiming);
        cudaEventCreateWithFlags(&evB, cudaEventDisableTiming);
        init_done = 1;
    }

    // fork: GEMM1 independent of graph build (dego applied per-edge in gather1)
    cudaEventRecord(evA, 0);
    cudaStreamWaitEvent(sB, evA, 0);

    zero_cnt_kernel<<<(NN + 255) / 256, 256>>>();                       // launch 0
    build_graph_kernel<<<(EE + 255) / 256, 256>>>(gsrc, gdst);          // launch 1
    make_scale_kernel<<<(NN + 255) / 256, 256>>>();                     // launch 2

    gemm128_kernel<<<(NN + 127) / 128, 512, GEMM_SMEM, sB>>>(feat, 0, W1, NN, 0); // launch 3

    cudaEventRecord(evB, sB);
    cudaStreamWaitEvent(0, evB, 0);

    gather_kernel<<<(NN + 7) / 8, 256>>>(b1, nullptr, 1);               // launch 4

    gemm128_kernel<<<(NN + 127) / 128, 512, GEMM_SMEM>>>(nullptr, 1, W2, NN, 1); // launch 5
    gather_kernel<<<(NN + 7) / 8, 256>>>(b2, out, 0);                   // launch 6

    edge_cls_kernel<<<(ECC + 7) / 8, 256>>>(out, csrc, cdst, Wc, bc,
                                            out + (size_t)NN * HH);     // launch 7
}